// round 16
// baseline (speedup 1.0000x reference)
#include <cuda_runtime.h>
#include <cuda_fp16.h>
#include <math.h>

#define Bn 4
#define Hn 512
#define Wn 512
#define Sn 40
#define PADc 32
#define OUTW 448
#define NPIX (Hn * Wn)

// ---------------- device scratch ----------------
__device__ __align__(16) float2 g_inc[Bn * NPIX];                // fp32 k-space field
__device__ __align__(16) unsigned g_b1h[Bn * NPIX];              // half2 scatter-path buffer
__device__ __align__(16) float2 g_b2[Bn * NPIX];                 // fp32 init/final buffer
__device__ __align__(16) float4 g_pg[NPIX];                      // (prop.x,prop.y,green.x,green.y)
__device__ __align__(16) float2 g_final[NPIX];
__device__ __align__(16) float2 g_tw[512];                       // exp(-2*pi*i*m/512)
__device__ __align__(16) unsigned g_sampH[(size_t)Sn * Bn * NPIX]; // half2 sample [s][b][h][w]

__device__ __forceinline__ float2 cadd(float2 a, float2 b) { return make_float2(a.x + b.x, a.y + b.y); }
__device__ __forceinline__ float2 csub(float2 a, float2 b) { return make_float2(a.x - b.x, a.y - b.y); }
__device__ __forceinline__ float2 cmul(float2 a, float2 b) {
    return make_float2(fmaf(a.x, b.x, -a.y * b.y), fmaf(a.x, b.y, a.y * b.x));
}
// multiply a by w, conjugating w when SIGN>0 (tables store forward e^{-i.})
template <int SIGN>
__device__ __forceinline__ float2 cmulw(float2 a, float2 w) {
    float wy = (SIGN > 0) ? -w.y : w.y;
    return make_float2(fmaf(a.x, w.x, -a.y * wy), fmaf(a.x, wy, a.y * w.x));
}

__device__ __forceinline__ void gbar(int id) {
    asm volatile("bar.sync %0, 64;" :: "r"(id) : "memory");
}

__device__ __forceinline__ unsigned packh2(float2 f) {
    __half2 h = __floats2half2_rn(f.x, f.y);
    return *reinterpret_cast<unsigned*>(&h);
}
__device__ __forceinline__ float2 unpackh2(unsigned u) {
    __half2 h = *reinterpret_cast<__half2*>(&u);
    return __half22float2(h);
}

// ---------------- 8-point DFT in registers ----------------
template <int SIGN>
__device__ __forceinline__ void fft8(float2* v) {
    const float s = (float)SIGN;
    const float r = 0.7071067811865476f;
    float2 t0 = cadd(v[0], v[4]), t1 = cadd(v[1], v[5]), t2 = cadd(v[2], v[6]), t3 = cadd(v[3], v[7]);
    float2 t4 = csub(v[0], v[4]), t5 = csub(v[1], v[5]), t6 = csub(v[2], v[6]), t7 = csub(v[3], v[7]);
    t5 = make_float2(r * t5.x - s * r * t5.y, s * r * t5.x + r * t5.y);
    t6 = make_float2(-s * t6.y, s * t6.x);
    t7 = make_float2(-r * t7.x - s * r * t7.y, s * r * t7.x - r * t7.y);
    float2 p0 = cadd(t0, t2), p2 = csub(t0, t2), p1 = cadd(t1, t3), p3 = csub(t1, t3);
    p3 = make_float2(-s * p3.y, s * p3.x);
    float2 q0 = cadd(t4, t6), q2 = csub(t4, t6), q1 = cadd(t5, t7), q3 = csub(t5, t7);
    q3 = make_float2(-s * q3.y, s * q3.x);
    v[0] = cadd(p0, p1); v[4] = csub(p0, p1); v[2] = cadd(p2, p3); v[6] = csub(p2, p3);
    v[1] = cadd(q0, q1); v[5] = csub(q0, q1); v[3] = cadd(q2, q3); v[7] = csub(q2, q3);
}

// apply v[k] *= W^k from entries W^1,W^2,W^4 (forward-signed), depth-2 products
template <int SIGN>
__device__ __forceinline__ void tw7_apply(float2* v, float2 a1, float2 a2, float2 a4) {
    float2 a3 = cmul(a2, a1);
    float2 a5 = cmul(a4, a1);
    float2 a6 = cmul(a4, a2);
    float2 a7 = cmul(a4, a3);
    v[1] = cmulw<SIGN>(v[1], a1);
    v[2] = cmulw<SIGN>(v[2], a2);
    v[3] = cmulw<SIGN>(v[3], a3);
    v[4] = cmulw<SIGN>(v[4], a4);
    v[5] = cmulw<SIGN>(v[5], a5);
    v[6] = cmulw<SIGN>(v[6], a6);
    v[7] = cmulw<SIGN>(v[7], a7);
}

// ---------------- 512-point FFT, double-buffered exchange, smem twiddle table --------
// entry: v[n1] = x[n1*64 + t]; exit: v[j2] = X[t + 64*j2]
// stw table block (216 float2): [w^t(64) | w^2t(64) | w^4t(64) | W8^m(8) | W8^2m(8) | W8^4m(8)]
// e0/e1: >=575 float2 each (stride-9 indexing, max index 574)
template <int SIGN, bool NAMED>
__device__ __forceinline__ void fft512_db(float2* v, float2* e0, float2* e1,
                                          const float2* stw, int t, int barid) {
    fft8<SIGN>(v);
    tw7_apply<SIGN>(v, stw[t], stw[64 + t], stw[128 + t]);     // w^{t k}
#pragma unroll
    for (int k = 0; k < 8; k++) e0[t * 9 + k] = v[k];
    if (NAMED) gbar(barid); else __syncthreads();
    const int m2 = t & 7, k1 = t >> 3;
#pragma unroll
    for (int m1 = 0; m1 < 8; m1++) v[m1] = e0[(m1 * 8 + m2) * 9 + k1];
    fft8<SIGN>(v);
    tw7_apply<SIGN>(v, stw[192 + m2], stw[200 + m2], stw[208 + m2]); // w^{8 m2 j}
#pragma unroll
    for (int j = 0; j < 8; j++) e1[(j * 8 + m2) * 9 + k1] = v[j];
    if (NAMED) gbar(barid); else __syncthreads();
    const int k1b = t & 7, j1 = t >> 3;
#pragma unroll
    for (int m = 0; m < 8; m++) v[m] = e1[(j1 * 8 + m) * 9 + k1b];
    fft8<SIGN>(v);
}

__device__ __forceinline__ void fill_tw(float2* stw, int flat) {
#pragma unroll
    for (int i = flat; i < 216; i += 128) {
        if (i < 64) stw[i] = g_tw[i];
        else if (i < 128) stw[i] = g_tw[2 * (i - 64)];
        else if (i < 192) stw[i] = g_tw[4 * (i - 128)];
        else if (i < 200) stw[i] = g_tw[8 * (i - 192)];
        else if (i < 208) stw[i] = g_tw[16 * (i - 200)];
        else stw[i] = g_tw[32 * (i - 208)];
    }
}

// ---------------- precompute ----------------
__global__ void k_tables(const float* __restrict__ kz, const float* __restrict__ oabs,
                         const float* __restrict__ gmask, const float* __restrict__ oph) {
    int w = threadIdx.x, h = blockIdx.x;
    if (h == 0) {
        float th = 6.283185307179586f * (float)w * (1.0f / 512.0f);
        float s, c;
        sincosf(th, &s, &c);
        g_tw[w] = make_float2(c, -s);
    }
    int idx = h * Wn + w;
    float k = kz[idx];
    float th = k * 0.1f;
    float s, cc;
    sincosf(th, &s, &cc);
    float inv2k = 0.5f / k;
    float m = gmask[idx];
    g_pg[idx] = make_float4(cc, s, -s * inv2k * m, cc * inv2k * m);
    float ph = oph[idx] - 5.0f * th;   // conj(prop^25)*prop^20 folded into otf
    float s2, c2;
    sincosf(ph, &s2, &c2);
    float a = oabs[idx];
    g_final[idx] = make_float2(a * c2, a * s2);
}

// ---------------- sample transpose [B,H,W,S] -> half2 [S,B,H,W] ----------------
__global__ void k_transpose(const float* __restrict__ re, const float* __restrict__ im) {
    __shared__ float2 tile[128 * Sn];
    const int wt = blockIdx.x;
    const int bh = blockIdx.y;
    const int b = bh / Hn, h = bh % Hn;
    const size_t base = ((size_t)bh * Wn + (size_t)wt * 128) * Sn;
    for (int t = threadIdx.x; t < 128 * Sn; t += 256)
        tile[t] = make_float2(re[base + t], im[base + t]);
    __syncthreads();
    for (int t = threadIdx.x; t < 128 * Sn; t += 256) {
        int s = t >> 7;
        int wp = t & 127;
        __stcs(&g_sampH[(((size_t)s * Bn + b) * Hn + h) * Wn + (size_t)wt * 128 + wp],
               packh2(tile[wp * Sn + s]));
    }
}

// ---------------- row kernels: block (64,2), named 2-warp barriers, grid 1024 --------
__global__ void __launch_bounds__(128) k_row_init(const float* __restrict__ pre,
                                                  const float* __restrict__ pim) {
    __shared__ __align__(16) float2 stw[216];
    __shared__ __align__(16) float2 ex[2][2][577];
    const int t = threadIdx.x, ly = threadIdx.y;
    const int line = blockIdx.x * 2 + ly;
    const size_t rb = (size_t)line * Wn;
    float2 v[8];
#pragma unroll
    for (int n1 = 0; n1 < 8; n1++) {
        int i = n1 * 64 + t;
        v[n1] = make_float2(pre[rb + i], pim[rb + i]);
    }
    fill_tw(stw, ly * 64 + t);
    __syncthreads();
    fft512_db<-1, true>(v, ex[ly][0], ex[ly][1], stw, t, ly + 1);
#pragma unroll
    for (int j = 0; j < 8; j++) g_b2[rb + t + 64 * j] = v[j];
}

// ifft-row -> *slab*dz (scaled) -> fft-row ; b1 half2 both ways
__global__ void __launch_bounds__(128) k_row_fused(int slice) {
    __shared__ __align__(16) float2 stw[216];
    __shared__ __align__(16) float2 ex[2][2][577];
    const int t = threadIdx.x, ly = threadIdx.y;
    const int line = blockIdx.x * 2 + ly;
    const size_t rb = (size_t)line * Wn;
    const unsigned* gs = g_sampH + (size_t)slice * (Bn * NPIX) + rb;
    // background L2 prefetch of slice s+1 (same line region): 2KB = 16 x 128B lines
    if (slice + 1 < Sn && t < 16) {
        const char* nx = (const char*)(gs + (size_t)Bn * NPIX) + t * 128;
        asm volatile("prefetch.global.L2 [%0];" :: "l"(nx));
    }
    float2 v[8];
    unsigned su[8];
#pragma unroll
    for (int j = 0; j < 8; j++) su[j] = __ldcs(gs + t + 64 * j);   // evict-first stream
#pragma unroll
    for (int n1 = 0; n1 < 8; n1++) v[n1] = unpackh2(g_b1h[rb + n1 * 64 + t]);
    fill_tw(stw, ly * 64 + t);
    __syncthreads();
    fft512_db<+1, true>(v, ex[ly][0], ex[ly][1], stw, t, ly + 1); // inverse row FFT
    const float sc = 0.1f / 512.0f;                               // DZ * (norm remainder)
#pragma unroll
    for (int j = 0; j < 8; j++) {
        float2 sl = unpackh2(su[j]);
        sl.x *= sc;
        sl.y *= sc;
        v[j] = cmul(v[j], sl);
    }
    fft512_db<-1, true>(v, ex[ly][0], ex[ly][1], stw, t, ly + 1); // forward row FFT
#pragma unroll
    for (int j = 0; j < 8; j++) g_b1h[rb + t + 64 * j] = packh2(v[j]);
}

// final inverse row + abs + crop (reads fp32 g_b2)
__global__ void __launch_bounds__(128) k_row_final(float* __restrict__ out) {
    __shared__ __align__(16) float2 stw[216];
    __shared__ __align__(16) float2 ex[2][2][577];
    const int t = threadIdx.x, ly = threadIdx.y;
    const int line = blockIdx.x * 2 + ly;                   // 0..B*OUTW-1
    const int b = line / OUTW;
    const int ho = line - b * OUTW;
    const size_t rb = ((size_t)b * Hn + ho + PADc) * Wn;
    float2 v[8];
#pragma unroll
    for (int n1 = 0; n1 < 8; n1++) v[n1] = g_b2[rb + n1 * 64 + t];
    fill_tw(stw, ly * 64 + t);
    __syncthreads();
    fft512_db<+1, true>(v, ex[ly][0], ex[ly][1], stw, t, ly + 1);
    const float sc = 1.0f / (512.0f * 512.0f);
    const size_t ob = ((size_t)b * OUTW + ho) * OUTW;
#pragma unroll
    for (int j = 0; j < 8; j++) {
        int i = t + 64 * j;
        if (i >= PADc && i < Wn - PADc)
            out[ob + i - PADc] = sqrtf(v[j].x * v[j].x + v[j].y * v[j].y) * sc;
    }
}

// ---------------- column kernel: block (4,64) = 4 cols, 5 blocks/SM, grid 512 --------
// MODE 0: inc = fftcol(b2 fp32); write inc; b1h = ifftcol(inc)/512
// MODE 1: inc = inc*prop + green*fftcol(b1h); write inc; b1h = ifftcol(inc)/512
// MODE 2: g_b2 = ifftcol((inc*prop + green*fftcol(b1h)) * final)   (fp32, no inc store)
// dynamic smem: stw[216] | per-col {e0[575], e1[575]} x 4 = 38,528 B
template <int MODE>
__global__ void __launch_bounds__(256, 5) k_col() {
    extern __shared__ __align__(16) float2 dsm[];
    float2* stw = dsm;
    const int c = threadIdx.x;     // 0..3
    const int ty = threadIdx.y;    // 0..63
    const int flat = ty * 4 + c;
    const int col = blockIdx.x * 4 + c;
    const size_t base = (size_t)blockIdx.y * NPIX;
    float2* e0 = dsm + 216 + c * 1150;
    float2* e1 = e0 + 575;
    float2 v[8];
#pragma unroll
    for (int n1 = 0; n1 < 8; n1++) {
        size_t gi = base + (size_t)(n1 * 64 + ty) * Wn + col;
        if (MODE == 0) v[n1] = g_b2[gi];
        else           v[n1] = unpackh2(g_b1h[gi]);
    }
    fill_tw(stw, flat);
    __syncthreads();
    fft512_db<-1, false>(v, e0, e1, stw, ty, 0);   // forward col FFT
#pragma unroll
    for (int j = 0; j < 8; j++) {
        int r = ty + 64 * j;
        size_t gi = base + (size_t)r * Wn + col;
        int hw = r * Wn + col;
        if (MODE == 0) {
            g_inc[gi] = v[j];
        } else {
            float4 pg = g_pg[hw];
            float2 u = cmul(g_inc[gi], make_float2(pg.x, pg.y));
            float2 s2 = cmul(make_float2(pg.z, pg.w), v[j]);
            float2 ni = cadd(u, s2);
            if (MODE == 1) {
                g_inc[gi] = ni;
                v[j] = ni;
            } else {
                v[j] = cmul(ni, g_final[hw]);
            }
        }
    }
    fft512_db<+1, false>(v, e0, e1, stw, ty, 0);   // inverse col FFT
    const float ws = 1.0f / 512.0f;
#pragma unroll
    for (int j = 0; j < 8; j++) {
        size_t gi = base + (size_t)(ty + 64 * j) * Wn + col;
        if (MODE == 2) {
            g_b2[gi] = v[j];
        } else {
            g_b1h[gi] = packh2(make_float2(v[j].x * ws, v[j].y * ws));
        }
    }
}

// ---------------- launch ----------------
extern "C" void kernel_launch(void* const* d_in, const int* in_sizes, int n_in,
                              void* d_out, int out_size) {
    (void)in_sizes; (void)n_in; (void)out_size;
    const float* sre  = (const float*)d_in[0];
    const float* sim  = (const float*)d_in[1];
    const float* pre  = (const float*)d_in[2];
    const float* pim  = (const float*)d_in[3];
    const float* kz   = (const float*)d_in[4];
    const float* oabs = (const float*)d_in[5];
    const float* gm   = (const float*)d_in[6];
    const float* oph  = (const float*)d_in[7];
    float* out = (float*)d_out;

    const int colSmem = (216 + 4 * 2 * 575) * (int)sizeof(float2);  // 38,528 B
    cudaFuncSetAttribute(k_col<0>, cudaFuncAttributeMaxDynamicSharedMemorySize, colSmem);
    cudaFuncSetAttribute(k_col<1>, cudaFuncAttributeMaxDynamicSharedMemorySize, colSmem);
    cudaFuncSetAttribute(k_col<2>, cudaFuncAttributeMaxDynamicSharedMemorySize, colSmem);

    k_tables<<<512, 512>>>(kz, oabs, gm, oph);
    k_transpose<<<dim3(Wn / 128, Bn * Hn), 256>>>(sre, sim);

    dim3 rowB(64, 2);
    dim3 colG(Wn / 4, Bn), colB(4, 64);

    k_row_init<<<Bn * Hn / 2, rowB>>>(pre, pim);
    k_col<0><<<colG, colB, colSmem>>>();

    for (int s = 0; s < Sn; s++) {
        k_row_fused<<<Bn * Hn / 2, rowB>>>(s);
        if (s < Sn - 1)
            k_col<1><<<colG, colB, colSmem>>>();
        else
            k_col<2><<<colG, colB, colSmem>>>();
    }

    k_row_final<<<Bn * OUTW / 2, rowB>>>(out);
}

// round 17
// speedup vs baseline: 1.2673x; 1.2673x over previous
#include <cuda_runtime.h>
#include <cuda_fp16.h>
#include <math.h>

#define Bn 4
#define Hn 512
#define Wn 512
#define Sn 40
#define PADc 32
#define OUTW 448
#define NPIX (Hn * Wn)

// ---------------- device scratch ----------------
__device__ __align__(16) float2 g_inc[Bn * NPIX];                // fp32 k-space field
__device__ __align__(16) unsigned g_b1h[Bn * NPIX];              // half2 scatter-path buffer
__device__ __align__(16) float2 g_b2[Bn * NPIX];                 // fp32 init/final buffer
__device__ __align__(16) float4 g_pg[NPIX];                      // (prop.x,prop.y,green.x,green.y)
__device__ __align__(16) float2 g_final[NPIX];
__device__ __align__(16) float2 g_tw[512];                       // exp(-2*pi*i*m/512)
__device__ __align__(16) unsigned g_sampH[(size_t)Sn * Bn * NPIX]; // half2 sample [s][b][h][w]

__device__ __forceinline__ float2 cadd(float2 a, float2 b) { return make_float2(a.x + b.x, a.y + b.y); }
__device__ __forceinline__ float2 csub(float2 a, float2 b) { return make_float2(a.x - b.x, a.y - b.y); }
__device__ __forceinline__ float2 cmul(float2 a, float2 b) {
    return make_float2(fmaf(a.x, b.x, -a.y * b.y), fmaf(a.x, b.y, a.y * b.x));
}
// multiply a by w, conjugating w when SIGN>0 (tables store forward e^{-i.})
template <int SIGN>
__device__ __forceinline__ float2 cmulw(float2 a, float2 w) {
    float wy = (SIGN > 0) ? -w.y : w.y;
    return make_float2(fmaf(a.x, w.x, -a.y * wy), fmaf(a.x, wy, a.y * w.x));
}

__device__ __forceinline__ void gbar(int id) {
    asm volatile("bar.sync %0, 64;" :: "r"(id) : "memory");
}

__device__ __forceinline__ unsigned packh2(float2 f) {
    __half2 h = __floats2half2_rn(f.x, f.y);
    return *reinterpret_cast<unsigned*>(&h);
}
__device__ __forceinline__ float2 unpackh2(unsigned u) {
    __half2 h = *reinterpret_cast<__half2*>(&u);
    return __half22float2(h);
}

// ---------------- 8-point DFT in registers ----------------
template <int SIGN>
__device__ __forceinline__ void fft8(float2* v) {
    const float s = (float)SIGN;
    const float r = 0.7071067811865476f;
    float2 t0 = cadd(v[0], v[4]), t1 = cadd(v[1], v[5]), t2 = cadd(v[2], v[6]), t3 = cadd(v[3], v[7]);
    float2 t4 = csub(v[0], v[4]), t5 = csub(v[1], v[5]), t6 = csub(v[2], v[6]), t7 = csub(v[3], v[7]);
    t5 = make_float2(r * t5.x - s * r * t5.y, s * r * t5.x + r * t5.y);
    t6 = make_float2(-s * t6.y, s * t6.x);
    t7 = make_float2(-r * t7.x - s * r * t7.y, s * r * t7.x - r * t7.y);
    float2 p0 = cadd(t0, t2), p2 = csub(t0, t2), p1 = cadd(t1, t3), p3 = csub(t1, t3);
    p3 = make_float2(-s * p3.y, s * p3.x);
    float2 q0 = cadd(t4, t6), q2 = csub(t4, t6), q1 = cadd(t5, t7), q3 = csub(t5, t7);
    q3 = make_float2(-s * q3.y, s * q3.x);
    v[0] = cadd(p0, p1); v[4] = csub(p0, p1); v[2] = cadd(p2, p3); v[6] = csub(p2, p3);
    v[1] = cadd(q0, q1); v[5] = csub(q0, q1); v[3] = cadd(q2, q3); v[7] = csub(q2, q3);
}

// apply v[k] *= W^k from entries W^1,W^2,W^4 (forward-signed), depth-2 products
template <int SIGN>
__device__ __forceinline__ void tw7_apply(float2* v, float2 a1, float2 a2, float2 a4) {
    float2 a3 = cmul(a2, a1);
    float2 a5 = cmul(a4, a1);
    float2 a6 = cmul(a4, a2);
    float2 a7 = cmul(a4, a3);
    v[1] = cmulw<SIGN>(v[1], a1);
    v[2] = cmulw<SIGN>(v[2], a2);
    v[3] = cmulw<SIGN>(v[3], a3);
    v[4] = cmulw<SIGN>(v[4], a4);
    v[5] = cmulw<SIGN>(v[5], a5);
    v[6] = cmulw<SIGN>(v[6], a6);
    v[7] = cmulw<SIGN>(v[7], a7);
}

// ---------------- 512-point FFT, double-buffered exchange, smem twiddle table --------
// entry: v[n1] = x[n1*64 + t]; exit: v[j2] = X[t + 64*j2]
// stw table block (216 float2): [w^t(64) | w^2t(64) | w^4t(64) | W8^m(8) | W8^2m(8) | W8^4m(8)]
// e0/e1: >=575 float2 each (stride-9 indexing, max index 574)
template <int SIGN, bool NAMED>
__device__ __forceinline__ void fft512_db(float2* v, float2* e0, float2* e1,
                                          const float2* stw, int t, int barid) {
    fft8<SIGN>(v);
    tw7_apply<SIGN>(v, stw[t], stw[64 + t], stw[128 + t]);     // w^{t k}
#pragma unroll
    for (int k = 0; k < 8; k++) e0[t * 9 + k] = v[k];
    if (NAMED) gbar(barid); else __syncthreads();
    const int m2 = t & 7, k1 = t >> 3;
#pragma unroll
    for (int m1 = 0; m1 < 8; m1++) v[m1] = e0[(m1 * 8 + m2) * 9 + k1];
    fft8<SIGN>(v);
    tw7_apply<SIGN>(v, stw[192 + m2], stw[200 + m2], stw[208 + m2]); // w^{8 m2 j}
#pragma unroll
    for (int j = 0; j < 8; j++) e1[(j * 8 + m2) * 9 + k1] = v[j];
    if (NAMED) gbar(barid); else __syncthreads();
    const int k1b = t & 7, j1 = t >> 3;
#pragma unroll
    for (int m = 0; m < 8; m++) v[m] = e1[(j1 * 8 + m) * 9 + k1b];
    fft8<SIGN>(v);
}

__device__ __forceinline__ void fill_tw(float2* stw, int flat) {
#pragma unroll
    for (int i = flat; i < 216; i += 128) {
        if (i < 64) stw[i] = g_tw[i];
        else if (i < 128) stw[i] = g_tw[2 * (i - 64)];
        else if (i < 192) stw[i] = g_tw[4 * (i - 128)];
        else if (i < 200) stw[i] = g_tw[8 * (i - 192)];
        else if (i < 208) stw[i] = g_tw[16 * (i - 200)];
        else stw[i] = g_tw[32 * (i - 208)];
    }
}

// ---------------- precompute ----------------
__global__ void k_tables(const float* __restrict__ kz, const float* __restrict__ oabs,
                         const float* __restrict__ gmask, const float* __restrict__ oph) {
    int w = threadIdx.x, h = blockIdx.x;
    if (h == 0) {
        float th = 6.283185307179586f * (float)w * (1.0f / 512.0f);
        float s, c;
        sincosf(th, &s, &c);
        g_tw[w] = make_float2(c, -s);
    }
    int idx = h * Wn + w;
    float k = kz[idx];
    float th = k * 0.1f;
    float s, cc;
    sincosf(th, &s, &cc);
    float inv2k = 0.5f / k;
    float m = gmask[idx];
    g_pg[idx] = make_float4(cc, s, -s * inv2k * m, cc * inv2k * m);
    float ph = oph[idx] - 5.0f * th;   // conj(prop^25)*prop^20 folded into otf
    float s2, c2;
    sincosf(ph, &s2, &c2);
    float a = oabs[idx];
    g_final[idx] = make_float2(a * c2, a * s2);
}

// ---------------- sample transpose [B,H,W,S] -> half2 [S,B,H,W] ----------------
__global__ void k_transpose(const float* __restrict__ re, const float* __restrict__ im) {
    __shared__ float2 tile[128 * Sn];
    const int wt = blockIdx.x;
    const int bh = blockIdx.y;
    const int b = bh / Hn, h = bh % Hn;
    const size_t base = ((size_t)bh * Wn + (size_t)wt * 128) * Sn;
    for (int t = threadIdx.x; t < 128 * Sn; t += 256)
        tile[t] = make_float2(re[base + t], im[base + t]);
    __syncthreads();
    for (int t = threadIdx.x; t < 128 * Sn; t += 256) {
        int s = t >> 7;
        int wp = t & 127;
        __stcs(&g_sampH[(((size_t)s * Bn + b) * Hn + h) * Wn + (size_t)wt * 128 + wp],
               packh2(tile[wp * Sn + s]));
    }
}

// ---------------- row kernels: block (64,4), named 2-warp barriers ----------------
__global__ void __launch_bounds__(256) k_row_init(const float* __restrict__ pre,
                                                  const float* __restrict__ pim) {
    __shared__ __align__(16) float2 stw[216];
    __shared__ __align__(16) float2 ex[4][2][577];
    const int t = threadIdx.x, ly = threadIdx.y;
    const int line = blockIdx.x * 4 + ly;
    const size_t rb = (size_t)line * Wn;
    float2 v[8];
#pragma unroll
    for (int n1 = 0; n1 < 8; n1++) {
        int i = n1 * 64 + t;
        v[n1] = make_float2(pre[rb + i], pim[rb + i]);
    }
    fill_tw(stw, ly * 64 + t);
    __syncthreads();
    fft512_db<-1, true>(v, ex[ly][0], ex[ly][1], stw, t, ly + 1);
#pragma unroll
    for (int j = 0; j < 8; j++) g_b2[rb + t + 64 * j] = v[j];
}

// ifft-row -> *slab*dz (scaled) -> fft-row ; b1 half2 both ways
__global__ void __launch_bounds__(256) k_row_fused(int slice) {
    __shared__ __align__(16) float2 stw[216];
    __shared__ __align__(16) float2 ex[4][2][577];
    const int t = threadIdx.x, ly = threadIdx.y;
    const int line = blockIdx.x * 4 + ly;
    const size_t rb = (size_t)line * Wn;
    const unsigned* gs = g_sampH + (size_t)slice * (Bn * NPIX) + rb;
    // background L2 prefetch of slice s+1 (same line region): 2KB = 16 x 128B lines
    if (slice + 1 < Sn && t < 16) {
        const char* nx = (const char*)(gs + (size_t)Bn * NPIX) + t * 128;
        asm volatile("prefetch.global.L2 [%0];" :: "l"(nx));
    }
    float2 v[8];
    unsigned su[8];
#pragma unroll
    for (int j = 0; j < 8; j++) su[j] = __ldcs(gs + t + 64 * j);   // evict-first stream
#pragma unroll
    for (int n1 = 0; n1 < 8; n1++) v[n1] = unpackh2(g_b1h[rb + n1 * 64 + t]);
    fill_tw(stw, ly * 64 + t);
    __syncthreads();
    fft512_db<+1, true>(v, ex[ly][0], ex[ly][1], stw, t, ly + 1); // inverse row FFT
    const float sc = 0.1f / 512.0f;                               // DZ * (norm remainder)
#pragma unroll
    for (int j = 0; j < 8; j++) {
        float2 sl = unpackh2(su[j]);
        sl.x *= sc;
        sl.y *= sc;
        v[j] = cmul(v[j], sl);
    }
    fft512_db<-1, true>(v, ex[ly][0], ex[ly][1], stw, t, ly + 1); // forward row FFT
#pragma unroll
    for (int j = 0; j < 8; j++) g_b1h[rb + t + 64 * j] = packh2(v[j]);
}

// final inverse row + abs + crop (reads fp32 g_b2)
__global__ void __launch_bounds__(256) k_row_final(float* __restrict__ out) {
    __shared__ __align__(16) float2 stw[216];
    __shared__ __align__(16) float2 ex[4][2][577];
    const int t = threadIdx.x, ly = threadIdx.y;
    const int line = blockIdx.x * 4 + ly;                   // 0..B*OUTW-1
    const int b = line / OUTW;
    const int ho = line - b * OUTW;
    const size_t rb = ((size_t)b * Hn + ho + PADc) * Wn;
    float2 v[8];
#pragma unroll
    for (int n1 = 0; n1 < 8; n1++) v[n1] = g_b2[rb + n1 * 64 + t];
    fill_tw(stw, ly * 64 + t);
    __syncthreads();
    fft512_db<+1, true>(v, ex[ly][0], ex[ly][1], stw, t, ly + 1);
    const float sc = 1.0f / (512.0f * 512.0f);
    const size_t ob = ((size_t)b * OUTW + ho) * OUTW;
#pragma unroll
    for (int j = 0; j < 8; j++) {
        int i = t + 64 * j;
        if (i >= PADc && i < Wn - PADc)
            out[ob + i - PADc] = sqrtf(v[j].x * v[j].x + v[j].y * v[j].y) * sc;
    }
}

// ---------------- column kernel: block (8,64), smem twiddles, inc reg-prefetch -------
// MODE 0: inc = fftcol(b2 fp32); write inc; b1h = ifftcol(inc)/512
// MODE 1: inc = inc*prop + green*fftcol(b1h); write inc; b1h = ifftcol(inc)/512
// MODE 2: g_b2 = ifftcol((inc*prop + green*fftcol(b1h)) * final)   (fp32, no inc store)
// dynamic smem: stw[216] | per-col {e0[575], e1[575]} x 8 = 75,328 B
template <int MODE>
__global__ void __launch_bounds__(512) k_col() {
    extern __shared__ __align__(16) float2 dsm[];
    float2* stw = dsm;
    const int c = threadIdx.x;     // 0..7
    const int ty = threadIdx.y;    // 0..63
    const int flat = ty * 8 + c;
    const int col = blockIdx.x * 8 + c;
    const size_t base = (size_t)blockIdx.y * NPIX;
    float2* e0 = dsm + 216 + c * 1150;
    float2* e1 = e0 + 575;
    float2 v[8];
    float2 inc0[8];
#pragma unroll
    for (int n1 = 0; n1 < 8; n1++) {
        size_t gi = base + (size_t)(n1 * 64 + ty) * Wn + col;
        if (MODE == 0) v[n1] = g_b2[gi];
        else           v[n1] = unpackh2(g_b1h[gi]);
    }
    if (MODE != 0) {
        // prefetch combine-phase inc into registers; consumed after forward FFT
#pragma unroll
        for (int j = 0; j < 8; j++)
            inc0[j] = g_inc[base + (size_t)(ty + 64 * j) * Wn + col];
    }
    fill_tw(stw, flat);
    __syncthreads();
    fft512_db<-1, false>(v, e0, e1, stw, ty, 0);   // forward col FFT
#pragma unroll
    for (int j = 0; j < 8; j++) {
        int r = ty + 64 * j;
        size_t gi = base + (size_t)r * Wn + col;
        int hw = r * Wn + col;
        if (MODE == 0) {
            g_inc[gi] = v[j];
        } else {
            float4 pg = g_pg[hw];
            float2 u = cmul(inc0[j], make_float2(pg.x, pg.y));
            float2 s2 = cmul(make_float2(pg.z, pg.w), v[j]);
            float2 ni = cadd(u, s2);
            if (MODE == 1) {
                g_inc[gi] = ni;
                v[j] = ni;
            } else {
                v[j] = cmul(ni, g_final[hw]);
            }
        }
    }
    fft512_db<+1, false>(v, e0, e1, stw, ty, 0);   // inverse col FFT
    const float ws = 1.0f / 512.0f;
#pragma unroll
    for (int j = 0; j < 8; j++) {
        size_t gi = base + (size_t)(ty + 64 * j) * Wn + col;
        if (MODE == 2) {
            g_b2[gi] = v[j];
        } else {
            g_b1h[gi] = packh2(make_float2(v[j].x * ws, v[j].y * ws));
        }
    }
}

// ---------------- launch ----------------
extern "C" void kernel_launch(void* const* d_in, const int* in_sizes, int n_in,
                              void* d_out, int out_size) {
    (void)in_sizes; (void)n_in; (void)out_size;
    const float* sre  = (const float*)d_in[0];
    const float* sim  = (const float*)d_in[1];
    const float* pre  = (const float*)d_in[2];
    const float* pim  = (const float*)d_in[3];
    const float* kz   = (const float*)d_in[4];
    const float* oabs = (const float*)d_in[5];
    const float* gm   = (const float*)d_in[6];
    const float* oph  = (const float*)d_in[7];
    float* out = (float*)d_out;

    const int colSmem = (216 + 8 * 2 * 575) * (int)sizeof(float2);  // 75,328 B
    cudaFuncSetAttribute(k_col<0>, cudaFuncAttributeMaxDynamicSharedMemorySize, colSmem);
    cudaFuncSetAttribute(k_col<1>, cudaFuncAttributeMaxDynamicSharedMemorySize, colSmem);
    cudaFuncSetAttribute(k_col<2>, cudaFuncAttributeMaxDynamicSharedMemorySize, colSmem);

    k_tables<<<512, 512>>>(kz, oabs, gm, oph);
    k_transpose<<<dim3(Wn / 128, Bn * Hn), 256>>>(sre, sim);

    dim3 rowB(64, 4);
    dim3 colG(Wn / 8, Bn), colB(8, 64);

    k_row_init<<<Bn * Hn / 4, rowB>>>(pre, pim);
    k_col<0><<<colG, colB, colSmem>>>();

    for (int s = 0; s < Sn; s++) {
        k_row_fused<<<Bn * Hn / 4, rowB>>>(s);
        if (s < Sn - 1)
            k_col<1><<<colG, colB, colSmem>>>();
        else
            k_col<2><<<colG, colB, colSmem>>>();
    }

    k_row_final<<<Bn * OUTW / 4, rowB>>>(out);
}